// round 5
// baseline (speedup 1.0000x reference)
#include <cuda_runtime.h>
#include <cuda_bf16.h>
#include <math.h>
#include <stdint.h>

// ---------------------------------------------------------------------------
// Problem constants
// ---------------------------------------------------------------------------
#define DM   768          // d_model
#define DI   1536         // d_inner
#define NS   16           // d_state
#define RK   48           // dt_rank
#define LC   6            // seq len
#define BT   1024         // batch
#define MR   (BT * LC)    // 6144 rows

// ---------------------------------------------------------------------------
// fp32 scratch (single __device__ array, no allocations)
// ---------------------------------------------------------------------------
#define OFF_XZ_F  ((size_t)0)
#define OFF_XZ_B  (OFF_XZ_F + 18874368u)
#define OFF_XC_F  (OFF_XZ_B + 18874368u)
#define OFF_XC_B  (OFF_XC_F + 9437184u)
#define OFF_XDP_F (OFF_XC_B + 9437184u)           // 4 split-K partials
#define OFF_XDP_B (OFF_XDP_F + 4u*491520u)
#define OFF_XD_F  (OFF_XDP_B + 4u*491520u)
#define OFF_XD_B  (OFF_XD_F + 491520u)
#define OFF_DT_F  (OFF_XD_B + 491520u)
#define OFF_DT_B  (OFF_DT_F + 9437184u)
#define OFF_R     (OFF_DT_B + 9437184u)
#define SCRATCH_TOTAL (OFF_R + 4718592u)

__device__ float g_scratch[SCRATCH_TOTAL];

// ---------------------------------------------------------------------------
// bf16 hi/lo plane scratch (hi plane followed by lo plane per buffer)
// ---------------------------------------------------------------------------
#define BO_X       ((size_t)0)          // 6144x768   plane 4718592
#define BO_WIN_F   ((size_t)9437184)    // 3072x768   plane 2359296
#define BO_WIN_B   ((size_t)14155776)
#define BO_WOUT_F  ((size_t)18874368)   // 768x1536   plane 1179648
#define BO_WOUT_B  ((size_t)21233664)
#define BO_XP_F    ((size_t)23592960)   // 128x1536   plane 196608 (rows>=80 zero)
#define BO_XP_B    ((size_t)23986176)
#define BO_DTW_F   ((size_t)24379392)   // 1536x64    plane 98304 (cols>=48 zero)
#define BO_DTW_B   ((size_t)24576000)
#define BO_XC_F    ((size_t)24772608)   // 6144x1536  plane 9437184
#define BO_XC_B    ((size_t)43646976)
#define BO_XDA_F   ((size_t)62521344)   // 6144x64    plane 393216 (cols>=48 zero)
#define BO_XDA_B   ((size_t)63307776)
#define BO_Y_F     ((size_t)64094208)   // 6144x1536  plane 9437184
#define BO_Y_B     ((size_t)82968576)
#define BF_TOTAL   ((size_t)101842944)

__device__ __nv_bfloat16 g_bf[BF_TOTAL];

#define PL_X    ((size_t)4718592)
#define PL_WIN  ((size_t)2359296)
#define PL_WOUT ((size_t)1179648)
#define PL_XP   ((size_t)196608)
#define PL_DTW  ((size_t)98304)
#define PL_XC   ((size_t)9437184)
#define PL_XDA  ((size_t)393216)
#define PL_Y    ((size_t)9437184)

// ---------------------------------------------------------------------------
// PTX helpers (plain sm_103 target legal)
// ---------------------------------------------------------------------------
__device__ __forceinline__ uint32_t smem_to_u32(const void* p) {
    uint32_t a;
    asm("{ .reg .u64 t; cvta.to.shared.u64 t, %1; cvt.u32.u64 %0, t; }"
        : "=r"(a) : "l"(p));
    return a;
}

__device__ __forceinline__ void ldsm4(uint32_t addr, uint32_t* r) {
    asm volatile("ldmatrix.sync.aligned.m8n8.x4.shared.b16 {%0, %1, %2, %3}, [%4];"
                 : "=r"(r[0]), "=r"(r[1]), "=r"(r[2]), "=r"(r[3]) : "r"(addr));
}

__device__ __forceinline__ void mma16816(float* c, const uint32_t* a,
                                         uint32_t b0, uint32_t b1) {
    asm volatile(
        "mma.sync.aligned.m16n8k16.row.col.f32.bf16.bf16.f32 "
        "{%0,%1,%2,%3}, {%4,%5,%6,%7}, {%8,%9}, {%0,%1,%2,%3};"
        : "+f"(c[0]), "+f"(c[1]), "+f"(c[2]), "+f"(c[3])
        : "r"(a[0]), "r"(a[1]), "r"(a[2]), "r"(a[3]), "r"(b0), "r"(b1));
}

__device__ __forceinline__ void cpa16(uint32_t s, const void* g) {
    asm volatile("cp.async.cg.shared.global [%0], [%1], 16;" :: "r"(s), "l"(g));
}
#define CP_COMMIT() asm volatile("cp.async.commit_group;" ::: "memory")
#define CP_WAIT(n)  asm volatile("cp.async.wait_group %0;" :: "n"(n) : "memory")

// fp32 pair -> (hi bf16x2, lo bf16x2); lo is the rounding residual
__device__ __forceinline__ void split2(float a0, float a1,
                                       uint32_t& hi, uint32_t& lo) {
    uint32_t h;
    asm("cvt.rn.bf16x2.f32 %0, %1, %2;" : "=r"(h) : "f"(a1), "f"(a0)); // lo half=a0
    float h0 = __uint_as_float(h << 16);
    float h1 = __uint_as_float(h & 0xffff0000u);
    float l0 = a0 - h0;
    float l1 = a1 - h1;
    asm("cvt.rn.bf16x2.f32 %0, %1, %2;" : "=r"(lo) : "f"(l1), "f"(l0));
    hi = h;
}

// ---------------------------------------------------------------------------
// Conversion / packing kernels (fp32 -> hi/lo bf16 planes)
// ---------------------------------------------------------------------------
__global__ void cvt_plane(const float* __restrict__ src, __nv_bfloat16* dst,
                          size_t plane, int npairs)
{
    const int i = blockIdx.x * 256 + threadIdx.x;
    if (i >= npairs) return;
    const float2 v = reinterpret_cast<const float2*>(src)[i];
    uint32_t hi, lo;
    split2(v.x, v.y, hi, lo);
    reinterpret_cast<uint32_t*>(dst)[i] = hi;
    reinterpret_cast<uint32_t*>(dst + plane)[i] = lo;
}

// x_proj weights (80,1536) -> padded (128,1536), rows >= 80 zero
__global__ void pad_xp(const float* __restrict__ src, __nv_bfloat16* dst)
{
    const int i = blockIdx.x * 256 + threadIdx.x;      // 98304 pairs
    const int e = i * 2;
    const int row = e / 1536, col = e % 1536;
    float a0 = 0.f, a1 = 0.f;
    if (row < 80) { a0 = src[row * 1536 + col]; a1 = src[row * 1536 + col + 1]; }
    uint32_t hi, lo;
    split2(a0, a1, hi, lo);
    reinterpret_cast<uint32_t*>(dst)[i] = hi;
    reinterpret_cast<uint32_t*>(dst + PL_XP)[i] = lo;
}

// dt weights (1536,48) -> padded (1536,64), cols >= 48 zero
__global__ void pad_dtw(const float* __restrict__ src, __nv_bfloat16* dst)
{
    const int i = blockIdx.x * 256 + threadIdx.x;      // 49152 pairs
    const int e = i * 2;
    const int row = e / 64, c = e % 64;
    float a0 = 0.f, a1 = 0.f;
    if (c < 48) { a0 = src[row * 48 + c]; a1 = src[row * 48 + c + 1]; }
    uint32_t hi, lo;
    split2(a0, a1, hi, lo);
    reinterpret_cast<uint32_t*>(dst)[i] = hi;
    reinterpret_cast<uint32_t*>(dst + PL_DTW)[i] = lo;
}

// xd (6144,80) cols 0..47 -> packed A' (6144,64), cols >= 48 zero
__global__ void pack_xda(const float* __restrict__ xd, __nv_bfloat16* dst)
{
    const int i = blockIdx.x * 256 + threadIdx.x;      // 196608 pairs
    const int e = i * 2;
    const int row = e / 64, c = e % 64;
    float a0 = 0.f, a1 = 0.f;
    if (c < 48) { a0 = xd[row * 80 + c]; a1 = xd[row * 80 + c + 1]; }
    uint32_t hi, lo;
    split2(a0, a1, hi, lo);
    reinterpret_cast<uint32_t*>(dst)[i] = hi;
    reinterpret_cast<uint32_t*>(dst + PL_XDA)[i] = lo;
}

// ---------------------------------------------------------------------------
// Split-precision bf16 tensor-core GEMM (NT), operands pre-converted:
//   C[.,N] = A[.,K](hi+lo, row, lda) @ B[N,K]^T(hi+lo, row, ldb)
// hi*hi + hi*lo + lo*hi (lo*lo dropped). CTA tile 128x128, BK=32, cp.async
// double-buffered. blockIdx.z = K-slice (C += z*czstride), koff = z*K.
// op: 0 = store (+addsrc), 1 = C += result, 2 = softplus(res + bias).
// nmax clips column writes (for padded N).
// ---------------------------------------------------------------------------
#define MG_STAGE 32768u          // sA(16KB) + sB(16KB)
#define MG_SMEM  (2u * MG_STAGE) // 64 KB

__global__ __launch_bounds__(256, 1)
void mma_bf16(int K,
              const __nv_bfloat16* __restrict__ Ah, int lda, size_t aplane,
              const __nv_bfloat16* __restrict__ Bh, int ldb, size_t bplane,
              float* __restrict__ C, int ldc, size_t czstride,
              const float* __restrict__ addsrc, const float* __restrict__ bias,
              int op, int nmax)
{
    extern __shared__ char dsm[];
    const uint32_t sbase = smem_to_u32(dsm);
    const int tid = threadIdx.x;
    const int w = tid >> 5, lane = tid & 31;
    const int bm = blockIdx.y * 128, bn = blockIdx.x * 128;
    const int wm = w & 3, wn = w >> 2;
    const int koff = blockIdx.z * K;
    C += (size_t)blockIdx.z * czstride;

    // loader: thread covers rows lrow, lrow+64 at 8-elem k-chunk lc
    const int lrow = tid >> 2, lc = tid & 3;
    const __nv_bfloat16* A0 = Ah + (size_t)(bm + lrow) * lda + koff + lc * 8;
    const __nv_bfloat16* B0 = Bh + (size_t)(bn + lrow) * ldb + koff + lc * 8;

    uint32_t dA[2][2], dB[2][2];   // [j][hi/lo] smem offsets within stage
#pragma unroll
    for (int j = 0; j < 2; j++) {
        const int r = lrow + j * 64;
        const uint32_t rb = (uint32_t)r * 128u;
        dA[j][0] = rb + (uint32_t)(((lc)     ^ (r & 7)) << 4);
        dA[j][1] = rb + (uint32_t)(((lc + 4) ^ (r & 7)) << 4);
        dB[j][0] = dA[j][0] + 16384u;
        dB[j][1] = dA[j][1] + 16384u;
    }

    const int S = K / 32;

    auto issue = [&](int s) {
        const uint32_t base = sbase + (uint32_t)(s & 1) * MG_STAGE;
        const size_t ko = (size_t)s * 32;
#pragma unroll
        for (int j = 0; j < 2; j++) {
            const __nv_bfloat16* ag = A0 + (size_t)j * 64 * lda + ko;
            const __nv_bfloat16* bg = B0 + (size_t)j * 64 * ldb + ko;
            cpa16(base + dA[j][0], ag);
            cpa16(base + dA[j][1], ag + aplane);
            cpa16(base + dB[j][0], bg);
            cpa16(base + dB[j][1], bg + bplane);
        }
        CP_COMMIT();
    };

    float acc[2][8][4];
#pragma unroll
    for (int i = 0; i < 2; i++)
#pragma unroll
        for (int j = 0; j < 8; j++)
#pragma unroll
            for (int t = 0; t < 4; t++) acc[i][j][t] = 0.f;

    issue(0);

    const int arow0 = wm * 32 + (lane & 15);
    const int ach   = lane >> 4;
    const int brow0 = wn * 64 + (lane & 7) + ((lane >> 4) & 1) * 8;
    const int bch   = (lane >> 3) & 1;

    for (int s = 0; s < S; s++) {
        if (s + 1 < S) { issue(s + 1); CP_WAIT(1); }
        else           { CP_WAIT(0); }
        __syncthreads();

        const uint32_t abase = sbase + (uint32_t)(s & 1) * MG_STAGE;
        const uint32_t bbase = abase + 16384u;
#pragma unroll
        for (int k2 = 0; k2 < 2; k2++) {
            const int kh  = k2 * 2 + ach;
            const int kl  = 4 + k2 * 2 + ach;
            const int kbh = k2 * 2 + bch;
            const int kbl = 4 + k2 * 2 + bch;
            uint32_t Ahi[2][4], Alo[2][4], Bhi[4][4], Blo[4][4];
#pragma unroll
            for (int mt = 0; mt < 2; mt++) {
                const int r = arow0 + mt * 16;
                const uint32_t rb = (uint32_t)r * 128u;
                ldsm4(abase + rb + (uint32_t)((kh ^ (r & 7)) << 4), Ahi[mt]);
                ldsm4(abase + rb + (uint32_t)((kl ^ (r & 7)) << 4), Alo[mt]);
            }
#pragma unroll
            for (int np = 0; np < 4; np++) {
                const int r = brow0 + np * 16;
                const uint32_t rb = (uint32_t)r * 128u;
                ldsm4(bbase + rb + (uint32_t)((kbh ^ (r & 7)) << 4), Bhi[np]);
                ldsm4(bbase + rb + (uint32_t)((kbl ^ (r & 7)) << 4), Blo[np]);
            }
#pragma unroll
            for (int mt = 0; mt < 2; mt++)
#pragma unroll
                for (int nt = 0; nt < 8; nt++) {
                    const uint32_t* bh = &Bhi[nt >> 1][(nt & 1) * 2];
                    const uint32_t* bl = &Blo[nt >> 1][(nt & 1) * 2];
                    mma16816(acc[mt][nt], Ahi[mt], bh[0], bh[1]);
                    mma16816(acc[mt][nt], Ahi[mt], bl[0], bl[1]);
                    mma16816(acc[mt][nt], Alo[mt], bh[0], bh[1]);
                }
        }
        __syncthreads();
    }

    // epilogue
    const int gid = lane >> 2, tig = lane & 3;
#pragma unroll
    for (int mt = 0; mt < 2; mt++)
#pragma unroll
        for (int hh = 0; hh < 2; hh++) {
            const int m = bm + wm * 32 + mt * 16 + gid + hh * 8;
            const int c0 = bn + wn * 64 + tig * 2;
            float* Crow = C + (size_t)m * ldc;
            const float* Ar = addsrc ? addsrc + (size_t)m * ldc : nullptr;
#pragma unroll
            for (int nt = 0; nt < 8; nt++) {
                const int n = c0 + nt * 8;
                if (n >= nmax) continue;
                float vx = acc[mt][nt][hh * 2];
                float vy = acc[mt][nt][hh * 2 + 1];
                if (Ar) {
                    float2 a = *reinterpret_cast<const float2*>(Ar + n);
                    vx += a.x; vy += a.y;
                }
                if (op == 1) {
                    float2 cv = *reinterpret_cast<const float2*>(Crow + n);
                    vx += cv.x; vy += cv.y;
                }
                if (op == 2) {
                    float2 bv = *reinterpret_cast<const float2*>(bias + n);
                    vx += bv.x; vy += bv.y;
                    vx = (vx > 20.f) ? vx : log1pf(expf(vx));
                    vy = (vy > 20.f) ? vy : log1pf(expf(vy));
                }
                *reinterpret_cast<float2*>(Crow + n) = make_float2(vx, vy);
            }
        }
}

// ---------------------------------------------------------------------------
// Depthwise causal conv (fwd) + anti-causal conv (bwd) + SiLU.
// Writes xc fp32 (for scan) and hi/lo bf16 planes (for xproj GEMM).
// ---------------------------------------------------------------------------
__global__ void conv_silu_kernel(const float* __restrict__ fw, const float* __restrict__ fb,
                                 const float* __restrict__ bw, const float* __restrict__ bb)
{
    const int idx = blockIdx.x * 256 + threadIdx.x;
    const int b = idx / DI, d = idx % DI;
    const float* xzf = g_scratch + OFF_XZ_F;
    const float* xzb = g_scratch + OFF_XZ_B;
    float* xcf = g_scratch + OFF_XC_F;
    float* xcb = g_scratch + OFF_XC_B;

    float wf[4], wbk[4];
#pragma unroll
    for (int k = 0; k < 4; k++) { wf[k] = fw[k * DI + d]; wbk[k] = bw[k * DI + d]; }

    float xf[6], xb[6];
#pragma unroll
    for (int l = 0; l < 6; l++) {
        xf[l] = xzf[(size_t)(b * 6 + l) * (2 * DI) + d];
        xb[l] = xzb[(size_t)(b * 6 + l) * (2 * DI) + d];
    }
    const float cbf = fb[d], cbb = bb[d];

#pragma unroll
    for (int l = 0; l < 6; l++) {
        float af = cbf, ab = cbb;
#pragma unroll
        for (int k = 0; k < 4; k++) {
            const int lf = l + k - 3;
            if (lf >= 0) af += wf[k] * xf[lf];
            const int lb = l + 3 - k;
            if (lb < 6) ab += wbk[k] * xb[lb];
        }
        const float sf = af / (1.f + expf(-af));
        const float sb = ab / (1.f + expf(-ab));
        const size_t o = (size_t)(b * 6 + l) * DI + d;
        xcf[o] = sf;
        xcb[o] = sb;
        __nv_bfloat16 hf = __float2bfloat16(sf);
        __nv_bfloat16 hb = __float2bfloat16(sb);
        g_bf[BO_XC_F + o] = hf;
        g_bf[BO_XC_F + PL_XC + o] = __float2bfloat16(sf - __bfloat162float(hf));
        g_bf[BO_XC_B + o] = hb;
        g_bf[BO_XC_B + PL_XC + o] = __float2bfloat16(sb - __bfloat162float(hb));
    }
}

// Sum the 4 split-K partials for both directions (deterministic).
__global__ void reduce4_kernel()
{
    const size_t S = (size_t)MR * 80;
    const size_t i = (size_t)blockIdx.x * 256 + threadIdx.x;
    const float* pf = g_scratch + OFF_XDP_F;
    const float* pb = g_scratch + OFF_XDP_B;
    g_scratch[OFF_XD_F + i] = (pf[i] + pf[i + S]) + (pf[i + 2 * S] + pf[i + 3 * S]);
    g_scratch[OFF_XD_B + i] = (pb[i] + pb[i + S]) + (pb[i + 2 * S] + pb[i + 3 * S]);
}

// ---------------------------------------------------------------------------
// Selective scan + skip (u*D) + SiLU(z) gate. Writes y as hi/lo bf16 planes.
// ---------------------------------------------------------------------------
__global__ __launch_bounds__(256)
void scan_kernel(int rev,
                 const float* __restrict__ dtb,
                 const float* __restrict__ ub,
                 const float* __restrict__ xzb,
                 const float* __restrict__ xdb,
                 const float* __restrict__ Alog,
                 const float* __restrict__ Dp,
                 size_t ybo)
{
    __shared__ float sB[6][16];
    __shared__ float sC[6][16];
    const int tid = threadIdx.x;
    const int b = blockIdx.y;
    const int d = blockIdx.x * 256 + tid;

    if (tid < 96) {
        const int l = tid >> 4, n = tid & 15;
        sB[l][n] = xdb[(size_t)(b * 6 + l) * 80 + 48 + n];
    } else if (tid < 192) {
        const int t = tid - 96;
        const int l = t >> 4, n = t & 15;
        sC[l][n] = xdb[(size_t)(b * 6 + l) * 80 + 64 + n];
    }
    __syncthreads();

    float A[16];
#pragma unroll
    for (int n = 0; n < 16; n++) A[n] = -expf(Alog[(size_t)d * 16 + n]);

    float h[16];
#pragma unroll
    for (int n = 0; n < 16; n++) h[n] = 0.f;
    const float Dd = Dp[d];

    for (int s = 0; s < 6; s++) {
        const int l = rev ? (5 - s) : s;
        const size_t row = (size_t)(b * 6 + l);
        const float dt = dtb[row * DI + d];
        const float u  = ub[row * DI + d];
        const float dtu = dt * u;
        float y = 0.f;
#pragma unroll
        for (int n = 0; n < 16; n++) {
            h[n] = expf(dt * A[n]) * h[n] + dtu * sB[l][n];
            y += h[n] * sC[l][n];
        }
        y += u * Dd;
        const float z = xzb[row * (2 * DI) + DI + d];
        y *= z / (1.f + expf(-z));
        const size_t o = row * DI + d;
        __nv_bfloat16 hy = __float2bfloat16(y);
        g_bf[ybo + o] = hy;
        g_bf[ybo + PL_Y + o] = __float2bfloat16(y - __bfloat162float(hy));
    }
}

// ---------------------------------------------------------------------------
// LayerNorm over the residual buffer r (MR x 768) -> d_out.
// ---------------------------------------------------------------------------
__device__ __forceinline__ float block_reduce_sum(float v)
{
    __shared__ float red[8];
    const int lane = threadIdx.x & 31, w = threadIdx.x >> 5;
#pragma unroll
    for (int o = 16; o; o >>= 1) v += __shfl_xor_sync(0xffffffffu, v, o);
    __syncthreads();
    if (lane == 0) red[w] = v;
    __syncthreads();
    return (red[0] + red[1]) + (red[2] + red[3]) +
           (red[4] + red[5]) + (red[6] + red[7]);
}

__global__ __launch_bounds__(256)
void ln_kernel(const float* __restrict__ g, const float* __restrict__ bta,
               float* __restrict__ out)
{
    const int row = blockIdx.x, tid = threadIdx.x;
    const float* r = g_scratch + OFF_R + (size_t)row * DM;
    const float v0 = r[tid], v1 = r[tid + 256], v2 = r[tid + 512];
    const float tot = block_reduce_sum(v0 + v1 + v2);
    const float mu = tot * (1.f / 768.f);
    const float d0 = v0 - mu, d1 = v1 - mu, d2 = v2 - mu;
    const float tot2 = block_reduce_sum(d0 * d0 + d1 * d1 + d2 * d2);
    const float inv = rsqrtf(tot2 * (1.f / 768.f) + 1e-5f);
    float* o = out + (size_t)row * DM;
    o[tid]       = d0 * inv * g[tid]       + bta[tid];
    o[tid + 256] = d1 * inv * g[tid + 256] + bta[tid + 256];
    o[tid + 512] = d2 * inv * g[tid + 512] + bta[tid + 512];
}

// ---------------------------------------------------------------------------
// Launch
// ---------------------------------------------------------------------------
extern "C" void kernel_launch(void* const* d_in, const int* in_sizes, int n_in,
                              void* d_out, int out_size)
{
    const float* x     = (const float*)d_in[0];
    const float* f_inw = (const float*)d_in[1];
    const float* f_cw  = (const float*)d_in[2];
    const float* f_cb  = (const float*)d_in[3];
    const float* f_xp  = (const float*)d_in[4];
    const float* f_dtw = (const float*)d_in[5];
    const float* f_dtb = (const float*)d_in[6];
    const float* f_Al  = (const float*)d_in[7];
    const float* f_D   = (const float*)d_in[8];
    const float* f_ow  = (const float*)d_in[9];
    const float* b_inw = (const float*)d_in[10];
    const float* b_cw  = (const float*)d_in[11];
    const float* b_cb  = (const float*)d_in[12];
    const float* b_xp  = (const float*)d_in[13];
    const float* b_dtw = (const float*)d_in[14];
    const float* b_dtb = (const float*)d_in[15];
    const float* b_Al  = (const float*)d_in[16];
    const float* b_D   = (const float*)d_in[17];
    const float* b_ow  = (const float*)d_in[18];
    const float* ln_g  = (const float*)d_in[19];
    const float* ln_b  = (const float*)d_in[20];
    float* out = (float*)d_out;

    float* S = nullptr;
    cudaGetSymbolAddress((void**)&S, g_scratch);
    __nv_bfloat16* BF = nullptr;
    cudaGetSymbolAddress((void**)&BF, g_bf);

    float* xz_f = S + OFF_XZ_F;
    float* xz_b = S + OFF_XZ_B;
    float* xc_f = S + OFF_XC_F;
    float* xc_b = S + OFF_XC_B;
    float* xdp_f = S + OFF_XDP_F;
    float* xdp_b = S + OFF_XDP_B;
    float* xd_f = S + OFF_XD_F;
    float* xd_b = S + OFF_XD_B;
    float* dt_f = S + OFF_DT_F;
    float* dt_b = S + OFF_DT_B;
    float* rbuf = S + OFF_R;

    cudaFuncSetAttribute(mma_bf16, cudaFuncAttributeMaxDynamicSharedMemorySize,
                         (int)MG_SMEM);

    const dim3 blk(256);

    // 0) pre-convert operands to hi/lo bf16 planes
    cvt_plane<<<9216, blk>>>(x,     BF + BO_X,      PL_X,    2359296);
    cvt_plane<<<4608, blk>>>(f_inw, BF + BO_WIN_F,  PL_WIN,  1179648);
    cvt_plane<<<4608, blk>>>(b_inw, BF + BO_WIN_B,  PL_WIN,  1179648);
    cvt_plane<<<2304, blk>>>(f_ow,  BF + BO_WOUT_F, PL_WOUT, 589824);
    cvt_plane<<<2304, blk>>>(b_ow,  BF + BO_WOUT_B, PL_WOUT, 589824);
    pad_xp<<<384, blk>>>(f_xp, BF + BO_XP_F);
    pad_xp<<<384, blk>>>(b_xp, BF + BO_XP_B);
    pad_dtw<<<192, blk>>>(f_dtw, BF + BO_DTW_F);
    pad_dtw<<<192, blk>>>(b_dtw, BF + BO_DTW_B);

    // 1) in_proj (both directions on un-reversed x)
    mma_bf16<<<dim3(24, 48, 1), blk, MG_SMEM>>>(DM, BF + BO_X, DM, PL_X,
        BF + BO_WIN_F, DM, PL_WIN, xz_f, 2 * DI, 0, nullptr, nullptr, 0, 2 * DI);
    mma_bf16<<<dim3(24, 48, 1), blk, MG_SMEM>>>(DM, BF + BO_X, DM, PL_X,
        BF + BO_WIN_B, DM, PL_WIN, xz_b, 2 * DI, 0, nullptr, nullptr, 0, 2 * DI);

    // 2) depthwise conv + SiLU (also emits xc bf16 planes)
    conv_silu_kernel<<<BT * DI / 256, blk>>>(f_cw, f_cb, b_cw, b_cb);

    // 3) x_proj: split-K=4 partials on tensor cores, deterministic reduce
    mma_bf16<<<dim3(1, 48, 4), blk, MG_SMEM>>>(384, BF + BO_XC_F, DI, PL_XC,
        BF + BO_XP_F, DI, PL_XP, xdp_f, 80, (size_t)MR * 80, nullptr, nullptr, 0, 80);
    mma_bf16<<<dim3(1, 48, 4), blk, MG_SMEM>>>(384, BF + BO_XC_B, DI, PL_XC,
        BF + BO_XP_B, DI, PL_XP, xdp_b, 80, (size_t)MR * 80, nullptr, nullptr, 0, 80);
    reduce4_kernel<<<(int)((size_t)MR * 80 / 256), blk>>>();
    pack_xda<<<768, blk>>>(xd_f, BF + BO_XDA_F);
    pack_xda<<<768, blk>>>(xd_b, BF + BO_XDA_B);

    // 4) dt projection + bias + softplus (K padded to 64, tensor cores)
    mma_bf16<<<dim3(12, 48, 1), blk, MG_SMEM>>>(64, BF + BO_XDA_F, 64, PL_XDA,
        BF + BO_DTW_F, 64, PL_DTW, dt_f, DI, 0, nullptr, f_dtb, 2, DI);
    mma_bf16<<<dim3(12, 48, 1), blk, MG_SMEM>>>(64, BF + BO_XDA_B, 64, PL_XDA,
        BF + BO_DTW_B, 64, PL_DTW, dt_b, DI, 0, nullptr, b_dtb, 2, DI);

    // 5) selective scan + D skip + SiLU(z) gate -> y bf16 planes
    scan_kernel<<<dim3(6, BT), blk>>>(0, dt_f, xc_f, xz_f, xd_f, f_Al, f_D, BO_Y_F);
    scan_kernel<<<dim3(6, BT), blk>>>(1, dt_b, xc_b, xz_b, xd_b, b_Al, b_D, BO_Y_B);

    // 6) out_proj (+x residual), second direction accumulates; then LayerNorm
    mma_bf16<<<dim3(6, 48, 1), blk, MG_SMEM>>>(DI, BF + BO_Y_F, DI, PL_Y,
        BF + BO_WOUT_F, DI, PL_WOUT, rbuf, DM, 0, x, nullptr, 0, DM);
    mma_bf16<<<dim3(6, 48, 1), blk, MG_SMEM>>>(DI, BF + BO_Y_B, DI, PL_Y,
        BF + BO_WOUT_B, DI, PL_WOUT, rbuf, DM, 0, nullptr, nullptr, 1, DM);
    ln_kernel<<<MR, blk>>>(ln_g, ln_b, out);
}

// round 6
// speedup vs baseline: 1.1765x; 1.1765x over previous
#include <cuda_runtime.h>
#include <cuda_fp16.h>
#include <math.h>
#include <stdint.h>

// ---------------------------------------------------------------------------
// Problem constants
// ---------------------------------------------------------------------------
#define DM   768          // d_model
#define DI   1536         // d_inner
#define NS   16           // d_state
#define RK   48           // dt_rank
#define LC   6            // seq len
#define BT   1024         // batch
#define MR   (BT * LC)    // 6144 rows

// ---------------------------------------------------------------------------
// fp32 scratch (single __device__ array, no allocations)
// ---------------------------------------------------------------------------
#define OFF_XZ_F  ((size_t)0)
#define OFF_XZ_B  (OFF_XZ_F + 18874368u)
#define OFF_XC_F  (OFF_XZ_B + 18874368u)
#define OFF_XC_B  (OFF_XC_F + 9437184u)
#define OFF_XDP_F (OFF_XC_B + 9437184u)           // 4 split-K partials
#define OFF_XDP_B (OFF_XDP_F + 4u*491520u)
#define OFF_XD_F  (OFF_XDP_B + 4u*491520u)
#define OFF_XD_B  (OFF_XD_F + 491520u)
#define OFF_DT_F  (OFF_XD_B + 491520u)
#define OFF_DT_B  (OFF_DT_F + 9437184u)
#define OFF_R     (OFF_DT_B + 9437184u)
#define SCRATCH_TOTAL (OFF_R + 4718592u)

__device__ float g_scratch[SCRATCH_TOTAL];

// ---------------------------------------------------------------------------
// fp16 scratch. Activations: single plane. Weights: hi plane + lo plane.
// ---------------------------------------------------------------------------
#define HO_X       ((size_t)0)          // 6144x768 single
#define HO_WIN_F   ((size_t)4718592)    // 3072x768, plane 2359296 (hi,lo)
#define HO_WIN_B   ((size_t)9437184)
#define HO_WOUT_F  ((size_t)14155776)   // 768x1536, plane 1179648
#define HO_WOUT_B  ((size_t)16515072)
#define HO_XP_F    ((size_t)18874368)   // 128x1536, plane 196608 (rows>=80 zero)
#define HO_XP_B    ((size_t)19267584)
#define HO_DTW_F   ((size_t)19660800)   // 1536x64, plane 98304 (cols>=48 zero)
#define HO_DTW_B   ((size_t)19857408)
#define HO_XC_F    ((size_t)20054016)   // 6144x1536 single
#define HO_XC_B    ((size_t)29491200)
#define HO_XDA_F   ((size_t)38928384)   // 6144x64 single (cols>=48 zero)
#define HO_XDA_B   ((size_t)39321600)
#define HO_Y_F     ((size_t)39714816)   // 6144x1536 single
#define HO_Y_B     ((size_t)49152000)
#define HF_TOTAL   ((size_t)58589184)

__device__ __align__(256) __half g_hf[HF_TOTAL];

#define PL_WIN  ((size_t)2359296)
#define PL_WOUT ((size_t)1179648)
#define PL_XP   ((size_t)196608)
#define PL_DTW  ((size_t)98304)

// ---------------------------------------------------------------------------
// PTX helpers (plain sm_103 target legal)
// ---------------------------------------------------------------------------
__device__ __forceinline__ uint32_t smem_to_u32(const void* p) {
    uint32_t a;
    asm("{ .reg .u64 t; cvta.to.shared.u64 t, %1; cvt.u32.u64 %0, t; }"
        : "=r"(a) : "l"(p));
    return a;
}

__device__ __forceinline__ void ldsm4(uint32_t addr, uint32_t* r) {
    asm volatile("ldmatrix.sync.aligned.m8n8.x4.shared.b16 {%0, %1, %2, %3}, [%4];"
                 : "=r"(r[0]), "=r"(r[1]), "=r"(r[2]), "=r"(r[3]) : "r"(addr));
}

__device__ __forceinline__ void mma16816h(float* c, const uint32_t* a,
                                          uint32_t b0, uint32_t b1) {
    asm volatile(
        "mma.sync.aligned.m16n8k16.row.col.f32.f16.f16.f32 "
        "{%0,%1,%2,%3}, {%4,%5,%6,%7}, {%8,%9}, {%0,%1,%2,%3};"
        : "+f"(c[0]), "+f"(c[1]), "+f"(c[2]), "+f"(c[3])
        : "r"(a[0]), "r"(a[1]), "r"(a[2]), "r"(a[3]), "r"(b0), "r"(b1));
}

__device__ __forceinline__ void cpa16(uint32_t s, const void* g) {
    asm volatile("cp.async.cg.shared.global [%0], [%1], 16;" :: "r"(s), "l"(g));
}
#define CP_COMMIT() asm volatile("cp.async.commit_group;" ::: "memory")
#define CP_WAIT(n)  asm volatile("cp.async.wait_group %0;" :: "n"(n) : "memory")

// fp32 pair -> (hi f16x2, lo f16x2); lo is the rounding residual
__device__ __forceinline__ void split2h(float a0, float a1,
                                        uint32_t& hi, uint32_t& lo) {
    __half h0 = __float2half_rn(a0), h1 = __float2half_rn(a1);
    __half l0 = __float2half_rn(a0 - __half2float(h0));
    __half l1 = __float2half_rn(a1 - __half2float(h1));
    hi = (uint32_t)__half_as_ushort(h0) | ((uint32_t)__half_as_ushort(h1) << 16);
    lo = (uint32_t)__half_as_ushort(l0) | ((uint32_t)__half_as_ushort(l1) << 16);
}
__device__ __forceinline__ uint32_t pack2h(float a0, float a1) {
    __half h0 = __float2half_rn(a0), h1 = __float2half_rn(a1);
    return (uint32_t)__half_as_ushort(h0) | ((uint32_t)__half_as_ushort(h1) << 16);
}

// ---------------------------------------------------------------------------
// Conversion / packing kernels
// ---------------------------------------------------------------------------
// fp32 -> single fp16 plane (activations)
__global__ void cvt_act(const float* __restrict__ src, __half* dst, int npairs)
{
    const int i = blockIdx.x * 256 + threadIdx.x;
    if (i >= npairs) return;
    const float2 v = reinterpret_cast<const float2*>(src)[i];
    reinterpret_cast<uint32_t*>(dst)[i] = pack2h(v.x, v.y);
}

// fp32 -> hi/lo fp16 planes (weights)
__global__ void cvt_w2(const float* __restrict__ src, __half* dst,
                       size_t plane, int npairs)
{
    const int i = blockIdx.x * 256 + threadIdx.x;
    if (i >= npairs) return;
    const float2 v = reinterpret_cast<const float2*>(src)[i];
    uint32_t hi, lo;
    split2h(v.x, v.y, hi, lo);
    reinterpret_cast<uint32_t*>(dst)[i] = hi;
    reinterpret_cast<uint32_t*>(dst + plane)[i] = lo;
}

// x_proj weights (80,1536) -> padded (128,1536) hi/lo, rows >= 80 zero
__global__ void pad_xp(const float* __restrict__ src, __half* dst)
{
    const int i = blockIdx.x * 256 + threadIdx.x;      // 98304 pairs
    const int e = i * 2;
    const int row = e / 1536, col = e % 1536;
    float a0 = 0.f, a1 = 0.f;
    if (row < 80) { a0 = src[row * 1536 + col]; a1 = src[row * 1536 + col + 1]; }
    uint32_t hi, lo;
    split2h(a0, a1, hi, lo);
    reinterpret_cast<uint32_t*>(dst)[i] = hi;
    reinterpret_cast<uint32_t*>(dst + PL_XP)[i] = lo;
}

// dt weights (1536,48) -> padded (1536,64) hi/lo, cols >= 48 zero
__global__ void pad_dtw(const float* __restrict__ src, __half* dst)
{
    const int i = blockIdx.x * 256 + threadIdx.x;      // 49152 pairs
    const int e = i * 2;
    const int row = e / 64, c = e % 64;
    float a0 = 0.f, a1 = 0.f;
    if (c < 48) { a0 = src[row * 48 + c]; a1 = src[row * 48 + c + 1]; }
    uint32_t hi, lo;
    split2h(a0, a1, hi, lo);
    reinterpret_cast<uint32_t*>(dst)[i] = hi;
    reinterpret_cast<uint32_t*>(dst + PL_DTW)[i] = lo;
}

// xd (6144,80) cols 0..47 -> packed (6144,64) single fp16, cols >= 48 zero
__global__ void pack_xda(const float* __restrict__ xd, __half* dst)
{
    const int i = blockIdx.x * 256 + threadIdx.x;      // 196608 pairs
    const int e = i * 2;
    const int row = e / 64, c = e % 64;
    float a0 = 0.f, a1 = 0.f;
    if (c < 48) { a0 = xd[row * 80 + c]; a1 = xd[row * 80 + c + 1]; }
    reinterpret_cast<uint32_t*>(dst)[i] = pack2h(a0, a1);
}

// ---------------------------------------------------------------------------
// Asymmetric-precision fp16 tensor-core GEMM (NT):
//   C[.,N] = A[.,K](fp16, row, lda) @ (Bhi + Blo)[N,K]^T(fp16, row, ldb)
// Two MMAs per tile: A*Bhi + A*Blo; only A's fp16 rounding error survives.
// CTA tile 128x128, BK=64 stages, cp.async double-buffered (96 KB smem).
// blockIdx.z = K-slice: koff = z*K, C += z*czstride.
// op: 0 = store (+addsrc), 1 = C += result, 2 = softplus(res + bias).
// nmax clips column writes (for padded N). Requires K%64==0.
// ---------------------------------------------------------------------------
#define HG_STAGE 49152u          // A(16KB) + Bhi(16KB) + Blo(16KB)
#define HG_SMEM  (2u * HG_STAGE) // 96 KB

__global__ __launch_bounds__(256, 1)
void mma_hf(int K,
            const __half* __restrict__ Ah, int lda,
            const __half* __restrict__ Bh, int ldb, size_t bplane,
            float* __restrict__ C, int ldc, size_t czstride,
            const float* __restrict__ addsrc, const float* __restrict__ bias,
            int op, int nmax)
{
    extern __shared__ char dsm[];
    const uint32_t sbase = smem_to_u32(dsm);
    const int tid = threadIdx.x;
    const int w = tid >> 5, lane = tid & 31;
    const int bm = blockIdx.y * 128, bn = blockIdx.x * 128;
    const int wm = w & 3, wn = w >> 2;
    const int koff = blockIdx.z * K;
    C += (size_t)blockIdx.z * czstride;

    // loader: thread handles row = tid>>1, 4 contiguous 16B chunks cg..cg+3
    const int lrow = tid >> 1, cg = (tid & 1) * 4;
    const __half* Aptr = Ah + (size_t)(bm + lrow) * lda + koff + cg * 8;
    const __half* Bptr = Bh + (size_t)(bn + lrow) * ldb + koff + cg * 8;

    uint32_t offs[4];
#pragma unroll
    for (int j = 0; j < 4; j++)
        offs[j] = (uint32_t)lrow * 128u + (uint32_t)(((cg + j) ^ (lrow & 7)) << 4);

    const int S = K / 64;

    auto issue = [&](int s) {
        const uint32_t base = sbase + (uint32_t)(s & 1) * HG_STAGE;
        const __half* ga = Aptr + (size_t)s * 64;
        const __half* gb = Bptr + (size_t)s * 64;
#pragma unroll
        for (int j = 0; j < 4; j++) {
            cpa16(base + offs[j], ga + j * 8);
            cpa16(base + 16384u + offs[j], gb + j * 8);
            cpa16(base + 32768u + offs[j], gb + bplane + j * 8);
        }
        CP_COMMIT();
    };

    float acc[2][8][4];
#pragma unroll
    for (int i = 0; i < 2; i++)
#pragma unroll
        for (int j = 0; j < 8; j++)
#pragma unroll
            for (int t = 0; t < 4; t++) acc[i][j][t] = 0.f;

    issue(0);

    const int arow0 = wm * 32 + (lane & 15);
    const int ach   = lane >> 4;
    const int brow0 = wn * 64 + (lane & 7) + ((lane >> 4) & 1) * 8;
    const int bch   = (lane >> 3) & 1;

    for (int s = 0; s < S; s++) {
        if (s + 1 < S) { issue(s + 1); CP_WAIT(1); }
        else           { CP_WAIT(0); }
        __syncthreads();

        const uint32_t abase  = sbase + (uint32_t)(s & 1) * HG_STAGE;
        const uint32_t bhbase = abase + 16384u;
        const uint32_t blbase = abase + 32768u;
#pragma unroll
        for (int k2 = 0; k2 < 4; k2++) {
            const int ka = k2 * 2 + ach;
            const int kb = k2 * 2 + bch;
            uint32_t Af[2][4], Bhi[4][4], Blo[4][4];
#pragma unroll
            for (int mt = 0; mt < 2; mt++) {
                const int r = arow0 + mt * 16;
                ldsm4(abase + (uint32_t)r * 128u + (uint32_t)((ka ^ (r & 7)) << 4), Af[mt]);
            }
#pragma unroll
            for (int np = 0; np < 4; np++) {
                const int r = brow0 + np * 16;
                const uint32_t ro = (uint32_t)r * 128u + (uint32_t)((kb ^ (r & 7)) << 4);
                ldsm4(bhbase + ro, Bhi[np]);
                ldsm4(blbase + ro, Blo[np]);
            }
#pragma unroll
            for (int mt = 0; mt < 2; mt++)
#pragma unroll
                for (int nt = 0; nt < 8; nt++) {
                    const uint32_t* bh = &Bhi[nt >> 1][(nt & 1) * 2];
                    const uint32_t* bl = &Blo[nt >> 1][(nt & 1) * 2];
                    mma16816h(acc[mt][nt], Af[mt], bh[0], bh[1]);
                    mma16816h(acc[mt][nt], Af[mt], bl[0], bl[1]);
                }
        }
        __syncthreads();
    }

    // epilogue
    const int gid = lane >> 2, tig = lane & 3;
#pragma unroll
    for (int mt = 0; mt < 2; mt++)
#pragma unroll
        for (int hh = 0; hh < 2; hh++) {
            const int m = bm + wm * 32 + mt * 16 + gid + hh * 8;
            const int c0 = bn + wn * 64 + tig * 2;
            float* Crow = C + (size_t)m * ldc;
            const float* Ar = addsrc ? addsrc + (size_t)m * ldc : nullptr;
#pragma unroll
            for (int nt = 0; nt < 8; nt++) {
                const int n = c0 + nt * 8;
                if (n >= nmax) continue;
                float vx = acc[mt][nt][hh * 2];
                float vy = acc[mt][nt][hh * 2 + 1];
                if (Ar) {
                    float2 a = *reinterpret_cast<const float2*>(Ar + n);
                    vx += a.x; vy += a.y;
                }
                if (op == 1) {
                    float2 cv = *reinterpret_cast<const float2*>(Crow + n);
                    vx += cv.x; vy += cv.y;
                }
                if (op == 2) {
                    float2 bv = *reinterpret_cast<const float2*>(bias + n);
                    vx += bv.x; vy += bv.y;
                    vx = (vx > 20.f) ? vx : log1pf(expf(vx));
                    vy = (vy > 20.f) ? vy : log1pf(expf(vy));
                }
                *reinterpret_cast<float2*>(Crow + n) = make_float2(vx, vy);
            }
        }
}

// ---------------------------------------------------------------------------
// Depthwise causal conv (fwd) + anti-causal conv (bwd) + SiLU.
// Writes xc fp32 (for scan) and a single fp16 plane (for xproj GEMM).
// ---------------------------------------------------------------------------
__global__ void conv_silu_kernel(const float* __restrict__ fw, const float* __restrict__ fb,
                                 const float* __restrict__ bw, const float* __restrict__ bb)
{
    const int idx = blockIdx.x * 256 + threadIdx.x;
    const int b = idx / DI, d = idx % DI;
    const float* xzf = g_scratch + OFF_XZ_F;
    const float* xzb = g_scratch + OFF_XZ_B;
    float* xcf = g_scratch + OFF_XC_F;
    float* xcb = g_scratch + OFF_XC_B;

    float wf[4], wbk[4];
#pragma unroll
    for (int k = 0; k < 4; k++) { wf[k] = fw[k * DI + d]; wbk[k] = bw[k * DI + d]; }

    float xf[6], xb[6];
#pragma unroll
    for (int l = 0; l < 6; l++) {
        xf[l] = xzf[(size_t)(b * 6 + l) * (2 * DI) + d];
        xb[l] = xzb[(size_t)(b * 6 + l) * (2 * DI) + d];
    }
    const float cbf = fb[d], cbb = bb[d];

#pragma unroll
    for (int l = 0; l < 6; l++) {
        float af = cbf, ab = cbb;
#pragma unroll
        for (int k = 0; k < 4; k++) {
            const int lf = l + k - 3;
            if (lf >= 0) af += wf[k] * xf[lf];
            const int lb = l + 3 - k;
            if (lb < 6) ab += wbk[k] * xb[lb];
        }
        const float sf = af / (1.f + expf(-af));
        const float sb = ab / (1.f + expf(-ab));
        const size_t o = (size_t)(b * 6 + l) * DI + d;
        xcf[o] = sf;
        xcb[o] = sb;
        g_hf[HO_XC_F + o] = __float2half_rn(sf);
        g_hf[HO_XC_B + o] = __float2half_rn(sb);
    }
}

// Sum the 4 split-K partials for both directions (deterministic).
__global__ void reduce4_kernel()
{
    const size_t S = (size_t)MR * 80;
    const size_t i = (size_t)blockIdx.x * 256 + threadIdx.x;
    const float* pf = g_scratch + OFF_XDP_F;
    const float* pb = g_scratch + OFF_XDP_B;
    g_scratch[OFF_XD_F + i] = (pf[i] + pf[i + S]) + (pf[i + 2 * S] + pf[i + 3 * S]);
    g_scratch[OFF_XD_B + i] = (pb[i] + pb[i + S]) + (pb[i + 2 * S] + pb[i + 3 * S]);
}

// ---------------------------------------------------------------------------
// Selective scan + skip (u*D) + SiLU(z) gate. Writes y as single fp16 plane.
// ---------------------------------------------------------------------------
__global__ __launch_bounds__(256)
void scan_kernel(int rev,
                 const float* __restrict__ dtb,
                 const float* __restrict__ ub,
                 const float* __restrict__ xzb,
                 const float* __restrict__ xdb,
                 const float* __restrict__ Alog,
                 const float* __restrict__ Dp,
                 size_t ybo)
{
    __shared__ float sB[6][16];
    __shared__ float sC[6][16];
    const int tid = threadIdx.x;
    const int b = blockIdx.y;
    const int d = blockIdx.x * 256 + tid;

    if (tid < 96) {
        const int l = tid >> 4, n = tid & 15;
        sB[l][n] = xdb[(size_t)(b * 6 + l) * 80 + 48 + n];
    } else if (tid < 192) {
        const int t = tid - 96;
        const int l = t >> 4, n = t & 15;
        sC[l][n] = xdb[(size_t)(b * 6 + l) * 80 + 64 + n];
    }
    __syncthreads();

    float A[16];
#pragma unroll
    for (int n = 0; n < 16; n++) A[n] = -expf(Alog[(size_t)d * 16 + n]);

    float h[16];
#pragma unroll
    for (int n = 0; n < 16; n++) h[n] = 0.f;
    const float Dd = Dp[d];

    for (int s = 0; s < 6; s++) {
        const int l = rev ? (5 - s) : s;
        const size_t row = (size_t)(b * 6 + l);
        const float dt = dtb[row * DI + d];
        const float u  = ub[row * DI + d];
        const float dtu = dt * u;
        float y = 0.f;
#pragma unroll
        for (int n = 0; n < 16; n++) {
            h[n] = expf(dt * A[n]) * h[n] + dtu * sB[l][n];
            y += h[n] * sC[l][n];
        }
        y += u * Dd;
        const float z = xzb[row * (2 * DI) + DI + d];
        y *= z / (1.f + expf(-z));
        g_hf[ybo + row * DI + d] = __float2half_rn(y);
    }
}

// ---------------------------------------------------------------------------
// LayerNorm over the residual buffer r (MR x 768) -> d_out.
// ---------------------------------------------------------------------------
__device__ __forceinline__ float block_reduce_sum(float v)
{
    __shared__ float red[8];
    const int lane = threadIdx.x & 31, w = threadIdx.x >> 5;
#pragma unroll
    for (int o = 16; o; o >>= 1) v += __shfl_xor_sync(0xffffffffu, v, o);
    __syncthreads();
    if (lane == 0) red[w] = v;
    __syncthreads();
    return (red[0] + red[1]) + (red[2] + red[3]) +
           (red[4] + red[5]) + (red[6] + red[7]);
}

__global__ __launch_bounds__(256)
void ln_kernel(const float* __restrict__ g, const float* __restrict__ bta,
               float* __restrict__ out)
{
    const int row = blockIdx.x, tid = threadIdx.x;
    const float* r = g_scratch + OFF_R + (size_t)row * DM;
    const float v0 = r[tid], v1 = r[tid + 256], v2 = r[tid + 512];
    const float tot = block_reduce_sum(v0 + v1 + v2);
    const float mu = tot * (1.f / 768.f);
    const float d0 = v0 - mu, d1 = v1 - mu, d2 = v2 - mu;
    const float tot2 = block_reduce_sum(d0 * d0 + d1 * d1 + d2 * d2);
    const float inv = rsqrtf(tot2 * (1.f / 768.f) + 1e-5f);
    float* o = out + (size_t)row * DM;
    o[tid]       = d0 * inv * g[tid]       + bta[tid];
    o[tid + 256] = d1 * inv * g[tid + 256] + bta[tid + 256];
    o[tid + 512] = d2 * inv * g[tid + 512] + bta[tid + 512];
}

// ---------------------------------------------------------------------------
// Launch
// ---------------------------------------------------------------------------
extern "C" void kernel_launch(void* const* d_in, const int* in_sizes, int n_in,
                              void* d_out, int out_size)
{
    const float* x     = (const float*)d_in[0];
    const float* f_inw = (const float*)d_in[1];
    const float* f_cw  = (const float*)d_in[2];
    const float* f_cb  = (const float*)d_in[3];
    const float* f_xp  = (const float*)d_in[4];
    const float* f_dtw = (const float*)d_in[5];
    const float* f_dtb = (const float*)d_in[6];
    const float* f_Al  = (const float*)d_in[7];
    const float* f_D   = (const float*)d_in[8];
    const float* f_ow  = (const float*)d_in[9];
    const float* b_inw = (const float*)d_in[10];
    const float* b_cw  = (const float*)d_in[11];
    const float* b_cb  = (const float*)d_in[12];
    const float* b_xp  = (const float*)d_in[13];
    const float* b_dtw = (const float*)d_in[14];
    const float* b_dtb = (const float*)d_in[15];
    const float* b_Al  = (const float*)d_in[16];
    const float* b_D   = (const float*)d_in[17];
    const float* b_ow  = (const float*)d_in[18];
    const float* ln_g  = (const float*)d_in[19];
    const float* ln_b  = (const float*)d_in[20];
    float* out = (float*)d_out;

    float* S = nullptr;
    cudaGetSymbolAddress((void**)&S, g_scratch);
    __half* HF = nullptr;
    cudaGetSymbolAddress((void**)&HF, g_hf);

    float* xz_f = S + OFF_XZ_F;
    float* xz_b = S + OFF_XZ_B;
    float* xc_f = S + OFF_XC_F;
    float* xc_b = S + OFF_XC_B;
    float* xdp_f = S + OFF_XDP_F;
    float* xdp_b = S + OFF_XDP_B;
    float* xd_f = S + OFF_XD_F;
    float* xd_b = S + OFF_XD_B;
    float* dt_f = S + OFF_DT_F;
    float* dt_b = S + OFF_DT_B;
    float* rbuf = S + OFF_R;

    cudaFuncSetAttribute(mma_hf, cudaFuncAttributeMaxDynamicSharedMemorySize,
                         (int)HG_SMEM);

    const dim3 blk(256);

    // 0) convert operands: activations single fp16, weights hi/lo fp16
    cvt_act<<<9216, blk>>>(x, HF + HO_X, 2359296);
    cvt_w2<<<4608, blk>>>(f_inw, HF + HO_WIN_F, PL_WIN, 1179648);
    cvt_w2<<<4608, blk>>>(b_inw, HF + HO_WIN_B, PL_WIN, 1179648);
    cvt_w2<<<2304, blk>>>(f_ow, HF + HO_WOUT_F, PL_WOUT, 589824);
    cvt_w2<<<2304, blk>>>(b_ow, HF + HO_WOUT_B, PL_WOUT, 589824);
    pad_xp<<<384, blk>>>(f_xp, HF + HO_XP_F);
    pad_xp<<<384, blk>>>(b_xp, HF + HO_XP_B);
    pad_dtw<<<192, blk>>>(f_dtw, HF + HO_DTW_F);
    pad_dtw<<<192, blk>>>(b_dtw, HF + HO_DTW_B);

    // 1) in_proj (both directions on un-reversed x)
    mma_hf<<<dim3(24, 48, 1), blk, HG_SMEM>>>(DM, HF + HO_X, DM,
        HF + HO_WIN_F, DM, PL_WIN, xz_f, 2 * DI, 0, nullptr, nullptr, 0, 2 * DI);
    mma_hf<<<dim3(24, 48, 1), blk, HG_SMEM>>>(DM, HF + HO_X, DM,
        HF + HO_WIN_B, DM, PL_WIN, xz_b, 2 * DI, 0, nullptr, nullptr, 0, 2 * DI);

    // 2) depthwise conv + SiLU (also emits xc fp16 plane)
    conv_silu_kernel<<<BT * DI / 256, blk>>>(f_cw, f_cb, b_cw, b_cb);

    // 3) x_proj: split-K=4 partials on tensor cores, deterministic reduce
    mma_hf<<<dim3(1, 48, 4), blk, HG_SMEM>>>(384, HF + HO_XC_F, DI,
        HF + HO_XP_F, DI, PL_XP, xdp_f, 80, (size_t)MR * 80, nullptr, nullptr, 0, 80);
    mma_hf<<<dim3(1, 48, 4), blk, HG_SMEM>>>(384, HF + HO_XC_B, DI,
        HF + HO_XP_B, DI, PL_XP, xdp_b, 80, (size_t)MR * 80, nullptr, nullptr, 0, 80);
    reduce4_kernel<<<(int)((size_t)MR * 80 / 256), blk>>>();
    pack_xda<<<768, blk>>>(xd_f, HF + HO_XDA_F);
    pack_xda<<<768, blk>>>(xd_b, HF + HO_XDA_B);

    // 4) dt projection + bias + softplus (K padded to 64, single stage)
    mma_hf<<<dim3(12, 48, 1), blk, HG_SMEM>>>(64, HF + HO_XDA_F, 64,
        HF + HO_DTW_F, 64, PL_DTW, dt_f, DI, 0, nullptr, f_dtb, 2, DI);
    mma_hf<<<dim3(12, 48, 1), blk, HG_SMEM>>>(64, HF + HO_XDA_B, 64,
        HF + HO_DTW_B, 64, PL_DTW, dt_b, DI, 0, nullptr, b_dtb, 2, DI);

    // 5) selective scan + D skip + SiLU(z) gate -> y fp16 plane
    scan_kernel<<<dim3(6, BT), blk>>>(0, dt_f, xc_f, xz_f, xd_f, f_Al, f_D, HO_Y_F);
    scan_kernel<<<dim3(6, BT), blk>>>(1, dt_b, xc_b, xz_b, xd_b, b_Al, b_D, HO_Y_B);

    // 6) out_proj (+x residual), second direction accumulates; then LayerNorm
    mma_hf<<<dim3(6, 48, 1), blk, HG_SMEM>>>(DI, HF + HO_Y_F, DI,
        HF + HO_WOUT_F, DI, PL_WOUT, rbuf, DM, 0, x, nullptr, 0, DM);
    mma_hf<<<dim3(6, 48, 1), blk, HG_SMEM>>>(DI, HF + HO_Y_B, DI,
        HF + HO_WOUT_B, DI, PL_WOUT, rbuf, DM, 0, nullptr, nullptr, 1, DM);
    ln_kernel<<<MR, blk>>>(ln_g, ln_b, out);
}

// round 7
// speedup vs baseline: 1.7324x; 1.4725x over previous
#include <cuda_runtime.h>
#include <cuda_fp16.h>
#include <math.h>
#include <stdint.h>

// ---------------------------------------------------------------------------
// Problem constants
// ---------------------------------------------------------------------------
#define DM   768          // d_model
#define DI   1536         // d_inner
#define NS   16           // d_state
#define RK   48           // dt_rank
#define LC   6            // seq len
#define BT   1024         // batch
#define MR   (BT * LC)    // 6144 rows

// ---------------------------------------------------------------------------
// fp32 scratch (single __device__ array, no allocations)
// ---------------------------------------------------------------------------
#define OFF_XZ_F  ((size_t)0)
#define OFF_XZ_B  (OFF_XZ_F + 18874368u)
#define OFF_XC_F  (OFF_XZ_B + 18874368u)
#define OFF_XC_B  (OFF_XC_F + 9437184u)
#define OFF_XDP_F (OFF_XC_B + 9437184u)           // 4 split-K partials
#define OFF_XDP_B (OFF_XDP_F + 4u*491520u)
#define OFF_XD_F  (OFF_XDP_B + 4u*491520u)
#define OFF_XD_B  (OFF_XD_F + 491520u)
#define OFF_DT_F  (OFF_XD_B + 491520u)
#define OFF_DT_B  (OFF_DT_F + 9437184u)
#define OFF_R     (OFF_DT_B + 9437184u)
#define SCRATCH_TOTAL (OFF_R + 4718592u)

__device__ float g_scratch[SCRATCH_TOTAL];

// ---------------------------------------------------------------------------
// fp16 scratch: single plane everywhere (pure fp16 operands, fp32 accum)
// ---------------------------------------------------------------------------
#define HO_X       ((size_t)0)          // 6144x768
#define HO_WIN_F   ((size_t)4718592)    // 3072x768
#define HO_WIN_B   ((size_t)7077888)
#define HO_WOUT_F  ((size_t)9437184)    // 768x1536
#define HO_WOUT_B  ((size_t)10616832)
#define HO_XP_F    ((size_t)11796480)   // 128x1536 (rows>=80 zero)
#define HO_XP_B    ((size_t)11993088)
#define HO_DTW_F   ((size_t)12189696)   // 1536x64 (cols>=48 zero)
#define HO_DTW_B   ((size_t)12288000)
#define HO_XC_F    ((size_t)12386304)   // 6144x1536
#define HO_XC_B    ((size_t)21823488)
#define HO_XDA_F   ((size_t)31260672)   // 6144x64 (cols>=48 zero)
#define HO_XDA_B   ((size_t)31653888)
#define HO_Y_F     ((size_t)32047104)   // 6144x1536
#define HO_Y_B     ((size_t)41484288)
#define HF_TOTAL   ((size_t)50921472)

__device__ __align__(256) __half g_hf[HF_TOTAL];

// ---------------------------------------------------------------------------
// PTX helpers (plain sm_103 target legal)
// ---------------------------------------------------------------------------
__device__ __forceinline__ uint32_t smem_to_u32(const void* p) {
    uint32_t a;
    asm("{ .reg .u64 t; cvta.to.shared.u64 t, %1; cvt.u32.u64 %0, t; }"
        : "=r"(a) : "l"(p));
    return a;
}

__device__ __forceinline__ void ldsm4(uint32_t addr, uint32_t* r) {
    asm volatile("ldmatrix.sync.aligned.m8n8.x4.shared.b16 {%0, %1, %2, %3}, [%4];"
                 : "=r"(r[0]), "=r"(r[1]), "=r"(r[2]), "=r"(r[3]) : "r"(addr));
}

__device__ __forceinline__ void mma16816h(float* c, const uint32_t* a,
                                          uint32_t b0, uint32_t b1) {
    asm volatile(
        "mma.sync.aligned.m16n8k16.row.col.f32.f16.f16.f32 "
        "{%0,%1,%2,%3}, {%4,%5,%6,%7}, {%8,%9}, {%0,%1,%2,%3};"
        : "+f"(c[0]), "+f"(c[1]), "+f"(c[2]), "+f"(c[3])
        : "r"(a[0]), "r"(a[1]), "r"(a[2]), "r"(a[3]), "r"(b0), "r"(b1));
}

__device__ __forceinline__ void cpa16(uint32_t s, const void* g) {
    asm volatile("cp.async.cg.shared.global [%0], [%1], 16;" :: "r"(s), "l"(g));
}
#define CP_COMMIT() asm volatile("cp.async.commit_group;" ::: "memory")
#define CP_WAIT(n)  asm volatile("cp.async.wait_group %0;" :: "n"(n) : "memory")

__device__ __forceinline__ uint32_t pack2h(float a0, float a1) {
    __half h0 = __float2half_rn(a0), h1 = __float2half_rn(a1);
    return (uint32_t)__half_as_ushort(h0) | ((uint32_t)__half_as_ushort(h1) << 16);
}

// ---------------------------------------------------------------------------
// Conversion / packing kernels (fp32 -> single fp16 plane)
// ---------------------------------------------------------------------------
__global__ void cvt_act(const float* __restrict__ src, __half* dst, int npairs)
{
    const int i = blockIdx.x * 256 + threadIdx.x;
    if (i >= npairs) return;
    const float2 v = reinterpret_cast<const float2*>(src)[i];
    reinterpret_cast<uint32_t*>(dst)[i] = pack2h(v.x, v.y);
}

// x_proj weights (80,1536) -> padded (128,1536), rows >= 80 zero
__global__ void pad_xp(const float* __restrict__ src, __half* dst)
{
    const int i = blockIdx.x * 256 + threadIdx.x;      // 98304 pairs
    const int e = i * 2;
    const int row = e / 1536, col = e % 1536;
    float a0 = 0.f, a1 = 0.f;
    if (row < 80) { a0 = src[row * 1536 + col]; a1 = src[row * 1536 + col + 1]; }
    reinterpret_cast<uint32_t*>(dst)[i] = pack2h(a0, a1);
}

// dt weights (1536,48) -> padded (1536,64), cols >= 48 zero
__global__ void pad_dtw(const float* __restrict__ src, __half* dst)
{
    const int i = blockIdx.x * 256 + threadIdx.x;      // 49152 pairs
    const int e = i * 2;
    const int row = e / 64, c = e % 64;
    float a0 = 0.f, a1 = 0.f;
    if (c < 48) { a0 = src[row * 48 + c]; a1 = src[row * 48 + c + 1]; }
    reinterpret_cast<uint32_t*>(dst)[i] = pack2h(a0, a1);
}

// xd (6144,80) cols 0..47 -> packed (6144,64) fp16, cols >= 48 zero
__global__ void pack_xda(const float* __restrict__ xd, __half* dst)
{
    const int i = blockIdx.x * 256 + threadIdx.x;      // 196608 pairs
    const int e = i * 2;
    const int row = e / 64, c = e % 64;
    float a0 = 0.f, a1 = 0.f;
    if (c < 48) { a0 = xd[row * 80 + c]; a1 = xd[row * 80 + c + 1]; }
    reinterpret_cast<uint32_t*>(dst)[i] = pack2h(a0, a1);
}

// ---------------------------------------------------------------------------
// Pure-fp16 tensor-core GEMM (NT), fp32 accumulate:
//   C[.,N] = A[.,K](fp16, row, lda) @ B[N,K]^T(fp16, row, ldb)
// CTA tile 128x128, BK=64 stages, cp.async double-buffered (64 KB smem).
// blockIdx.z = K-slice: koff = z*K, C += z*czstride.
// op: 0 = store (+addsrc), 1 = C += result, 2 = softplus(res + bias).
// nmax clips column writes (for padded N). Requires K%64==0.
// ---------------------------------------------------------------------------
#define HG_STAGE 32768u          // A(16KB) + B(16KB)
#define HG_SMEM  (2u * HG_STAGE) // 64 KB

__global__ __launch_bounds__(256)
void mma_hf(int K,
            const __half* __restrict__ Ah, int lda,
            const __half* __restrict__ Bh, int ldb,
            float* __restrict__ C, int ldc, size_t czstride,
            const float* __restrict__ addsrc, const float* __restrict__ bias,
            int op, int nmax)
{
    extern __shared__ char dsm[];
    const uint32_t sbase = smem_to_u32(dsm);
    const int tid = threadIdx.x;
    const int w = tid >> 5, lane = tid & 31;
    const int bm = blockIdx.y * 128, bn = blockIdx.x * 128;
    const int wm = w & 3, wn = w >> 2;
    const int koff = blockIdx.z * K;
    C += (size_t)blockIdx.z * czstride;

    // loader: thread handles row = tid>>1, 4 contiguous 16B chunks cg..cg+3
    const int lrow = tid >> 1, cg = (tid & 1) * 4;
    const __half* Aptr = Ah + (size_t)(bm + lrow) * lda + koff + cg * 8;
    const __half* Bptr = Bh + (size_t)(bn + lrow) * ldb + koff + cg * 8;

    uint32_t offs[4];
#pragma unroll
    for (int j = 0; j < 4; j++)
        offs[j] = (uint32_t)lrow * 128u + (uint32_t)(((cg + j) ^ (lrow & 7)) << 4);

    const int S = K / 64;

    auto issue = [&](int s) {
        const uint32_t base = sbase + (uint32_t)(s & 1) * HG_STAGE;
        const __half* ga = Aptr + (size_t)s * 64;
        const __half* gb = Bptr + (size_t)s * 64;
#pragma unroll
        for (int j = 0; j < 4; j++) {
            cpa16(base + offs[j], ga + j * 8);
            cpa16(base + 16384u + offs[j], gb + j * 8);
        }
        CP_COMMIT();
    };

    float acc[2][8][4];
#pragma unroll
    for (int i = 0; i < 2; i++)
#pragma unroll
        for (int j = 0; j < 8; j++)
#pragma unroll
            for (int t = 0; t < 4; t++) acc[i][j][t] = 0.f;

    issue(0);

    const int arow0 = wm * 32 + (lane & 15);
    const int ach   = lane >> 4;
    const int brow0 = wn * 64 + (lane & 7) + ((lane >> 4) & 1) * 8;
    const int bch   = (lane >> 3) & 1;

    for (int s = 0; s < S; s++) {
        if (s + 1 < S) { issue(s + 1); CP_WAIT(1); }
        else           { CP_WAIT(0); }
        __syncthreads();

        const uint32_t abase = sbase + (uint32_t)(s & 1) * HG_STAGE;
        const uint32_t bbase = abase + 16384u;
#pragma unroll
        for (int k2 = 0; k2 < 4; k2++) {
            const int ka = k2 * 2 + ach;
            const int kb = k2 * 2 + bch;
            uint32_t Af[2][4], Bf[4][4];
#pragma unroll
            for (int mt = 0; mt < 2; mt++) {
                const int r = arow0 + mt * 16;
                ldsm4(abase + (uint32_t)r * 128u + (uint32_t)((ka ^ (r & 7)) << 4), Af[mt]);
            }
#pragma unroll
            for (int np = 0; np < 4; np++) {
                const int r = brow0 + np * 16;
                ldsm4(bbase + (uint32_t)r * 128u + (uint32_t)((kb ^ (r & 7)) << 4), Bf[np]);
            }
#pragma unroll
            for (int mt = 0; mt < 2; mt++)
#pragma unroll
                for (int nt = 0; nt < 8; nt++) {
                    const uint32_t* bp = &Bf[nt >> 1][(nt & 1) * 2];
                    mma16816h(acc[mt][nt], Af[mt], bp[0], bp[1]);
                }
        }
        __syncthreads();
    }

    // epilogue
    const int gid = lane >> 2, tig = lane & 3;
#pragma unroll
    for (int mt = 0; mt < 2; mt++)
#pragma unroll
        for (int hh = 0; hh < 2; hh++) {
            const int m = bm + wm * 32 + mt * 16 + gid + hh * 8;
            const int c0 = bn + wn * 64 + tig * 2;
            float* Crow = C + (size_t)m * ldc;
            const float* Ar = addsrc ? addsrc + (size_t)m * ldc : nullptr;
#pragma unroll
            for (int nt = 0; nt < 8; nt++) {
                const int n = c0 + nt * 8;
                if (n >= nmax) continue;
                float vx = acc[mt][nt][hh * 2];
                float vy = acc[mt][nt][hh * 2 + 1];
                if (Ar) {
                    float2 a = *reinterpret_cast<const float2*>(Ar + n);
                    vx += a.x; vy += a.y;
                }
                if (op == 1) {
                    float2 cv = *reinterpret_cast<const float2*>(Crow + n);
                    vx += cv.x; vy += cv.y;
                }
                if (op == 2) {
                    float2 bv = *reinterpret_cast<const float2*>(bias + n);
                    vx += bv.x; vy += bv.y;
                    vx = (vx > 20.f) ? vx : log1pf(expf(vx));
                    vy = (vy > 20.f) ? vy : log1pf(expf(vy));
                }
                *reinterpret_cast<float2*>(Crow + n) = make_float2(vx, vy);
            }
        }
}

// ---------------------------------------------------------------------------
// Depthwise causal conv (fwd) + anti-causal conv (bwd) + SiLU.
// Writes xc fp32 (for scan) and a single fp16 plane (for xproj GEMM).
// ---------------------------------------------------------------------------
__global__ void conv_silu_kernel(const float* __restrict__ fw, const float* __restrict__ fb,
                                 const float* __restrict__ bw, const float* __restrict__ bb)
{
    const int idx = blockIdx.x * 256 + threadIdx.x;
    const int b = idx / DI, d = idx % DI;
    const float* xzf = g_scratch + OFF_XZ_F;
    const float* xzb = g_scratch + OFF_XZ_B;
    float* xcf = g_scratch + OFF_XC_F;
    float* xcb = g_scratch + OFF_XC_B;

    float wf[4], wbk[4];
#pragma unroll
    for (int k = 0; k < 4; k++) { wf[k] = fw[k * DI + d]; wbk[k] = bw[k * DI + d]; }

    float xf[6], xb[6];
#pragma unroll
    for (int l = 0; l < 6; l++) {
        xf[l] = xzf[(size_t)(b * 6 + l) * (2 * DI) + d];
        xb[l] = xzb[(size_t)(b * 6 + l) * (2 * DI) + d];
    }
    const float cbf = fb[d], cbb = bb[d];

#pragma unroll
    for (int l = 0; l < 6; l++) {
        float af = cbf, ab = cbb;
#pragma unroll
        for (int k = 0; k < 4; k++) {
            const int lf = l + k - 3;
            if (lf >= 0) af += wf[k] * xf[lf];
            const int lb = l + 3 - k;
            if (lb < 6) ab += wbk[k] * xb[lb];
        }
        const float sf = af / (1.f + expf(-af));
        const float sb = ab / (1.f + expf(-ab));
        const size_t o = (size_t)(b * 6 + l) * DI + d;
        xcf[o] = sf;
        xcb[o] = sb;
        g_hf[HO_XC_F + o] = __float2half_rn(sf);
        g_hf[HO_XC_B + o] = __float2half_rn(sb);
    }
}

// Sum the 4 split-K partials for both directions (deterministic).
__global__ void reduce4_kernel()
{
    const size_t S = (size_t)MR * 80;
    const size_t i = (size_t)blockIdx.x * 256 + threadIdx.x;
    const float* pf = g_scratch + OFF_XDP_F;
    const float* pb = g_scratch + OFF_XDP_B;
    g_scratch[OFF_XD_F + i] = (pf[i] + pf[i + S]) + (pf[i + 2 * S] + pf[i + 3 * S]);
    g_scratch[OFF_XD_B + i] = (pb[i] + pb[i + S]) + (pb[i + 2 * S] + pb[i + 3 * S]);
}

// ---------------------------------------------------------------------------
// Selective scan + skip (u*D) + SiLU(z) gate. Writes y as fp16 plane.
// ---------------------------------------------------------------------------
__global__ __launch_bounds__(256)
void scan_kernel(int rev,
                 const float* __restrict__ dtb,
                 const float* __restrict__ ub,
                 const float* __restrict__ xzb,
                 const float* __restrict__ xdb,
                 const float* __restrict__ Alog,
                 const float* __restrict__ Dp,
                 size_t ybo)
{
    __shared__ float sB[6][16];
    __shared__ float sC[6][16];
    const int tid = threadIdx.x;
    const int b = blockIdx.y;
    const int d = blockIdx.x * 256 + tid;

    if (tid < 96) {
        const int l = tid >> 4, n = tid & 15;
        sB[l][n] = xdb[(size_t)(b * 6 + l) * 80 + 48 + n];
    } else if (tid < 192) {
        const int t = tid - 96;
        const int l = t >> 4, n = t & 15;
        sC[l][n] = xdb[(size_t)(b * 6 + l) * 80 + 64 + n];
    }
    __syncthreads();

    float A[16];
#pragma unroll
    for (int n = 0; n < 16; n++) A[n] = -expf(Alog[(size_t)d * 16 + n]);

    float h[16];
#pragma unroll
    for (int n = 0; n < 16; n++) h[n] = 0.f;
    const float Dd = Dp[d];

    for (int s = 0; s < 6; s++) {
        const int l = rev ? (5 - s) : s;
        const size_t row = (size_t)(b * 6 + l);
        const float dt = dtb[row * DI + d];
        const float u  = ub[row * DI + d];
        const float dtu = dt * u;
        float y = 0.f;
#pragma unroll
        for (int n = 0; n < 16; n++) {
            h[n] = expf(dt * A[n]) * h[n] + dtu * sB[l][n];
            y += h[n] * sC[l][n];
        }
        y += u * Dd;
        const float z = xzb[row * (2 * DI) + DI + d];
        y *= z / (1.f + expf(-z));
        g_hf[ybo + row * DI + d] = __float2half_rn(y);
    }
}

// ---------------------------------------------------------------------------
// LayerNorm over the residual buffer r (MR x 768) -> d_out.
// ---------------------------------------------------------------------------
__device__ __forceinline__ float block_reduce_sum(float v)
{
    __shared__ float red[8];
    const int lane = threadIdx.x & 31, w = threadIdx.x >> 5;
#pragma unroll
    for (int o = 16; o; o >>= 1) v += __shfl_xor_sync(0xffffffffu, v, o);
    __syncthreads();
    if (lane == 0) red[w] = v;
    __syncthreads();
    return (red[0] + red[1]) + (red[2] + red[3]) +
           (red[4] + red[5]) + (red[6] + red[7]);
}

__global__ __launch_bounds__(256)
void ln_kernel(const float* __restrict__ g, const float* __restrict__ bta,
               float* __restrict__ out)
{
    const int row = blockIdx.x, tid = threadIdx.x;
    const float* r = g_scratch + OFF_R + (size_t)row * DM;
    const float v0 = r[tid], v1 = r[tid + 256], v2 = r[tid + 512];
    const float tot = block_reduce_sum(v0 + v1 + v2);
    const float mu = tot * (1.f / 768.f);
    const float d0 = v0 - mu, d1 = v1 - mu, d2 = v2 - mu;
    const float tot2 = block_reduce_sum(d0 * d0 + d1 * d1 + d2 * d2);
    const float inv = rsqrtf(tot2 * (1.f / 768.f) + 1e-5f);
    float* o = out + (size_t)row * DM;
    o[tid]       = d0 * inv * g[tid]       + bta[tid];
    o[tid + 256] = d1 * inv * g[tid + 256] + bta[tid + 256];
    o[tid + 512] = d2 * inv * g[tid + 512] + bta[tid + 512];
}

// ---------------------------------------------------------------------------
// Launch
// ---------------------------------------------------------------------------
extern "C" void kernel_launch(void* const* d_in, const int* in_sizes, int n_in,
                              void* d_out, int out_size)
{
    const float* x     = (const float*)d_in[0];
    const float* f_inw = (const float*)d_in[1];
    const float* f_cw  = (const float*)d_in[2];
    const float* f_cb  = (const float*)d_in[3];
    const float* f_xp  = (const float*)d_in[4];
    const float* f_dtw = (const float*)d_in[5];
    const float* f_dtb = (const float*)d_in[6];
    const float* f_Al  = (const float*)d_in[7];
    const float* f_D   = (const float*)d_in[8];
    const float* f_ow  = (const float*)d_in[9];
    const float* b_inw = (const float*)d_in[10];
    const float* b_cw  = (const float*)d_in[11];
    const float* b_cb  = (const float*)d_in[12];
    const float* b_xp  = (const float*)d_in[13];
    const float* b_dtw = (const float*)d_in[14];
    const float* b_dtb = (const float*)d_in[15];
    const float* b_Al  = (const float*)d_in[16];
    const float* b_D   = (const float*)d_in[17];
    const float* b_ow  = (const float*)d_in[18];
    const float* ln_g  = (const float*)d_in[19];
    const float* ln_b  = (const float*)d_in[20];
    float* out = (float*)d_out;

    float* S = nullptr;
    cudaGetSymbolAddress((void**)&S, g_scratch);
    __half* HF = nullptr;
    cudaGetSymbolAddress((void**)&HF, g_hf);

    float* xz_f = S + OFF_XZ_F;
    float* xz_b = S + OFF_XZ_B;
    float* xc_f = S + OFF_XC_F;
    float* xc_b = S + OFF_XC_B;
    float* xdp_f = S + OFF_XDP_F;
    float* xdp_b = S + OFF_XDP_B;
    float* xd_f = S + OFF_XD_F;
    float* xd_b = S + OFF_XD_B;
    float* dt_f = S + OFF_DT_F;
    float* dt_b = S + OFF_DT_B;
    float* rbuf = S + OFF_R;

    cudaFuncSetAttribute(mma_hf, cudaFuncAttributeMaxDynamicSharedMemorySize,
                         (int)HG_SMEM);

    const dim3 blk(256);

    // 0) convert all GEMM operands to single fp16 planes
    cvt_act<<<9216, blk>>>(x, HF + HO_X, 2359296);
    cvt_act<<<4608, blk>>>(f_inw, HF + HO_WIN_F, 1179648);
    cvt_act<<<4608, blk>>>(b_inw, HF + HO_WIN_B, 1179648);
    cvt_act<<<2304, blk>>>(f_ow, HF + HO_WOUT_F, 589824);
    cvt_act<<<2304, blk>>>(b_ow, HF + HO_WOUT_B, 589824);
    pad_xp<<<384, blk>>>(f_xp, HF + HO_XP_F);
    pad_xp<<<384, blk>>>(b_xp, HF + HO_XP_B);
    pad_dtw<<<192, blk>>>(f_dtw, HF + HO_DTW_F);
    pad_dtw<<<192, blk>>>(b_dtw, HF + HO_DTW_B);

    // 1) in_proj (both directions on un-reversed x)
    mma_hf<<<dim3(24, 48, 1), blk, HG_SMEM>>>(DM, HF + HO_X, DM,
        HF + HO_WIN_F, DM, xz_f, 2 * DI, 0, nullptr, nullptr, 0, 2 * DI);
    mma_hf<<<dim3(24, 48, 1), blk, HG_SMEM>>>(DM, HF + HO_X, DM,
        HF + HO_WIN_B, DM, xz_b, 2 * DI, 0, nullptr, nullptr, 0, 2 * DI);

    // 2) depthwise conv + SiLU (also emits xc fp16 plane)
    conv_silu_kernel<<<BT * DI / 256, blk>>>(f_cw, f_cb, b_cw, b_cb);

    // 3) x_proj: split-K=4 partials on tensor cores, deterministic reduce
    mma_hf<<<dim3(1, 48, 4), blk, HG_SMEM>>>(384, HF + HO_XC_F, DI,
        HF + HO_XP_F, DI, xdp_f, 80, (size_t)MR * 80, nullptr, nullptr, 0, 80);
    mma_hf<<<dim3(1, 48, 4), blk, HG_SMEM>>>(384, HF + HO_XC_B, DI,
        HF + HO_XP_B, DI, xdp_b, 80, (size_t)MR * 80, nullptr, nullptr, 0, 80);
    reduce4_kernel<<<(int)((size_t)MR * 80 / 256), blk>>>();
    pack_xda<<<768, blk>>>(xd_f, HF + HO_XDA_F);
    pack_xda<<<768, blk>>>(xd_b, HF + HO_XDA_B);

    // 4) dt projection + bias + softplus (K padded to 64, single stage)
    mma_hf<<<dim3(12, 48, 1), blk, HG_SMEM>>>(64, HF + HO_XDA_F, 64,
        HF + HO_DTW_F, 64, dt_f, DI, 0, nullptr, f_dtb, 2, DI);
    mma_hf<<<dim3(12, 48, 1), blk, HG_SMEM>>>(64, HF + HO_XDA_B, 64,
        HF + HO_DTW_B, 64, dt_b, DI, 0, nullptr, b_dtb, 2, DI);

    // 5) selective scan + D skip + SiLU(z) gate -> y fp16 plane
    scan_kernel<<<dim3(6, BT), blk>>>(0, dt_f, xc_f, xz_f, xd_f, f_Al, f_D, HO_Y_F);
    scan_kernel<<<dim3(6, BT), blk>>>(1, dt_b, xc_b, xz_b, xd_b, b_Al, b_D, HO_Y_B);

    // 6) out_proj (+x residual), second direction accumulates; then LayerNorm
    mma_hf<<<dim3(6, 48, 1), blk, HG_SMEM>>>(DI, HF + HO_Y_F, DI,
        HF + HO_WOUT_F, DI, rbuf, DM, 0, x, nullptr, 0, DM);
    mma_hf<<<dim3(6, 48, 1), blk, HG_SMEM>>>(DI, HF + HO_Y_B, DI,
        HF + HO_WOUT_B, DI, rbuf, DM, 0, nullptr, nullptr, 1, DM);
    ln_kernel<<<MR, blk>>>(ln_g, ln_b, out);
}